// round 2
// baseline (speedup 1.0000x reference)
#include <cuda_runtime.h>

#define B_  2
#define LQ  1024
#define LK  2048
#define DM  1024
#define NH  16
#define DH  64

typedef unsigned long long u64;

// packed fp32x2 FMA (sm_100+ PTX; exact fp32, 2 FLOPs per fma-pipe slot)
__device__ __forceinline__ u64 fma2(u64 a, u64 b, u64 c) {
    asm("fma.rn.f32x2 %0, %1, %2, %3;" : "=l"(c) : "l"(a), "l"(b), "l"(c));
    return c;
}
__device__ __forceinline__ float2 u2f(u64 v) {
    float2 f;
    f.x = __int_as_float((int)(v & 0xffffffffull));
    f.y = __int_as_float((int)(v >> 32));
    return f;
}

// ---------------- scratch (device globals; no allocation allowed) ----------
__device__ float g_Q[B_*NH*LQ*DH];
__device__ float g_K[B_*NH*LK*DH];
__device__ float g_V[B_*NH*LK*DH];
__device__ float g_Ctx[B_*LQ*DM];
__device__ float g_attn_fallback[(size_t)B_*NH*LQ*LK];

// ---------------------------------------------------------------------------
// C = X @ W^T + bias.  128x128 tile, BK=8, 256 threads, 8x8 microtile, fma2.
// ---------------------------------------------------------------------------
__global__ __launch_bounds__(256, 2)
void proj_gemm(const float* __restrict__ X, const float* __restrict__ W,
               const float* __restrict__ bias, float* __restrict__ out,
               int L, int headSplit)
{
    __shared__ __align__(16) float As[8][132];
    __shared__ __align__(16) float Bs[8][132];
    __shared__ __align__(16) float Bw[8][132];   // pair-swapped along n
    const int tid = threadIdx.x;
    const int m0 = blockIdx.y * 128;
    const int n0 = blockIdx.x * 128;
    const int tx = tid & 15, ty = tid >> 4;

    u64 accD[4][4], accA[4][4];
    #pragma unroll
    for (int p = 0; p < 4; p++)
        #pragma unroll
        for (int q = 0; q < 4; q++) { accD[p][q] = 0ull; accA[p][q] = 0ull; }

    const int lr = tid >> 1;        // tile row 0..127
    const int lc = (tid & 1) * 4;   // k offset 0 or 4
    const float* Xp = X + (size_t)(m0 + lr) * DM + lc;
    const float* Wp = W + (size_t)(n0 + lr) * DM + lc;

    for (int k0 = 0; k0 < DM; k0 += 8) {
        float4 xa = *(const float4*)(Xp + k0);
        float4 wb = *(const float4*)(Wp + k0);
        As[lc+0][lr] = xa.x; As[lc+1][lr] = xa.y; As[lc+2][lr] = xa.z; As[lc+3][lr] = xa.w;
        Bs[lc+0][lr] = wb.x; Bs[lc+1][lr] = wb.y; Bs[lc+2][lr] = wb.z; Bs[lc+3][lr] = wb.w;
        int ls = lr ^ 1;
        Bw[lc+0][ls] = wb.x; Bw[lc+1][ls] = wb.y; Bw[lc+2][ls] = wb.z; Bw[lc+3][ls] = wb.w;
        __syncthreads();
        #pragma unroll
        for (int k = 0; k < 8; k++) {
            ulonglong2 a01 = *(const ulonglong2*)&As[k][ty*8];
            ulonglong2 a23 = *(const ulonglong2*)&As[k][ty*8+4];
            ulonglong2 b01 = *(const ulonglong2*)&Bs[k][tx*8];
            ulonglong2 b23 = *(const ulonglong2*)&Bs[k][tx*8+4];
            ulonglong2 w01 = *(const ulonglong2*)&Bw[k][tx*8];
            ulonglong2 w23 = *(const ulonglong2*)&Bw[k][tx*8+4];
            u64 ap[4] = {a01.x, a01.y, a23.x, a23.y};
            u64 bp[4] = {b01.x, b01.y, b23.x, b23.y};
            u64 bw[4] = {w01.x, w01.y, w23.x, w23.y};
            #pragma unroll
            for (int p = 0; p < 4; p++)
                #pragma unroll
                for (int q = 0; q < 4; q++) {
                    accD[p][q] = fma2(ap[p], bp[q], accD[p][q]);
                    accA[p][q] = fma2(ap[p], bw[q], accA[p][q]);
                }
        }
        __syncthreads();
    }

    float c[8][8];
    #pragma unroll
    for (int p = 0; p < 4; p++)
        #pragma unroll
        for (int q = 0; q < 4; q++) {
            float2 d_ = u2f(accD[p][q]);
            float2 a_ = u2f(accA[p][q]);
            c[2*p  ][2*q  ] = d_.x;
            c[2*p+1][2*q+1] = d_.y;
            c[2*p  ][2*q+1] = a_.x;
            c[2*p+1][2*q  ] = a_.y;
        }

    const int nb = n0 + tx*8;
    float4 bia0 = *(const float4*)&bias[nb];
    float4 bia1 = *(const float4*)&bias[nb+4];
    #pragma unroll
    for (int i = 0; i < 8; i++) {
        int m = m0 + ty*8 + i;
        float4 v0 = make_float4(c[i][0]+bia0.x, c[i][1]+bia0.y, c[i][2]+bia0.z, c[i][3]+bia0.w);
        float4 v1 = make_float4(c[i][4]+bia1.x, c[i][5]+bia1.y, c[i][6]+bia1.z, c[i][7]+bia1.w);
        if (headSplit) {
            int b = m / L, l = m - b * L;
            int h = nb >> 6, d = nb & 63;          // 8-wide chunk stays in one head
            float* o = out + (((size_t)b*NH + h)*L + l)*DH + d;
            *(float4*)o = v0;
            *(float4*)(o+4) = v1;
        } else {
            float* o = out + (size_t)m*DM + nb;
            *(float4*)o = v0;
            *(float4*)(o+4) = v1;
        }
    }
}

// ---------------------------------------------------------------------------
// scores: S[b,h,q,k] = (Q.K)/8 + bias, masked -> -1e9.
// 128x128 tile over dh=64, BK=16, 8x8 microtile, fma2.
// ---------------------------------------------------------------------------
__global__ __launch_bounds__(256, 2)
void scores_kernel(const int* __restrict__ mask, const float* __restrict__ bias,
                   float* __restrict__ P)
{
    const int bh = blockIdx.z;
    const int b  = bh / NH;
    const int q0 = blockIdx.y * 128;
    const int k0 = blockIdx.x * 128;
    __shared__ __align__(16) float As[16][132];   // [d][q]
    __shared__ __align__(16) float Bs[16][132];   // [d][k]
    __shared__ __align__(16) float Bw[16][132];   // pair-swapped along k
    const float* Qg = g_Q + ((size_t)bh*LQ + q0) * DH;
    const float* Kg = g_K + ((size_t)bh*LK + k0) * DH;
    const int tid = threadIdx.x;
    const int tx = tid & 15, ty = tid >> 4;

    u64 accD[4][4], accA[4][4];
    #pragma unroll
    for (int p = 0; p < 4; p++)
        #pragma unroll
        for (int q = 0; q < 4; q++) { accD[p][q] = 0ull; accA[p][q] = 0ull; }

    for (int d0 = 0; d0 < DH; d0 += 16) {
        #pragma unroll
        for (int it = 0; it < 2; it++) {
            int g = tid + it * 256;       // 0..511 float4 granules
            int r = g >> 2;               // 0..127
            int cc = (g & 3) * 4;         // 0,4,8,12
            float4 qv = *(const float4*)(Qg + (size_t)r*DH + d0 + cc);
            As[cc+0][r]=qv.x; As[cc+1][r]=qv.y; As[cc+2][r]=qv.z; As[cc+3][r]=qv.w;
            float4 kv = *(const float4*)(Kg + (size_t)r*DH + d0 + cc);
            Bs[cc+0][r]=kv.x; Bs[cc+1][r]=kv.y; Bs[cc+2][r]=kv.z; Bs[cc+3][r]=kv.w;
            int rs = r ^ 1;
            Bw[cc+0][rs]=kv.x; Bw[cc+1][rs]=kv.y; Bw[cc+2][rs]=kv.z; Bw[cc+3][rs]=kv.w;
        }
        __syncthreads();
        #pragma unroll
        for (int k = 0; k < 16; k++) {
            ulonglong2 a01 = *(const ulonglong2*)&As[k][ty*8];
            ulonglong2 a23 = *(const ulonglong2*)&As[k][ty*8+4];
            ulonglong2 b01 = *(const ulonglong2*)&Bs[k][tx*8];
            ulonglong2 b23 = *(const ulonglong2*)&Bs[k][tx*8+4];
            ulonglong2 w01 = *(const ulonglong2*)&Bw[k][tx*8];
            ulonglong2 w23 = *(const ulonglong2*)&Bw[k][tx*8+4];
            u64 ap[4] = {a01.x, a01.y, a23.x, a23.y};
            u64 bp[4] = {b01.x, b01.y, b23.x, b23.y};
            u64 bw[4] = {w01.x, w01.y, w23.x, w23.y};
            #pragma unroll
            for (int p = 0; p < 4; p++)
                #pragma unroll
                for (int q = 0; q < 4; q++) {
                    accD[p][q] = fma2(ap[p], bp[q], accD[p][q]);
                    accA[p][q] = fma2(ap[p], bw[q], accA[p][q]);
                }
        }
        __syncthreads();
    }

    float c[8][8];
    #pragma unroll
    for (int p = 0; p < 4; p++)
        #pragma unroll
        for (int q = 0; q < 4; q++) {
            float2 d_ = u2f(accD[p][q]);
            float2 a_ = u2f(accA[p][q]);
            c[2*p  ][2*q  ] = d_.x;
            c[2*p+1][2*q+1] = d_.y;
            c[2*p  ][2*q+1] = a_.x;
            c[2*p+1][2*q  ] = a_.y;
        }

    const int kb = k0 + tx*8;
    #pragma unroll
    for (int i = 0; i < 8; i++) {
        int q = q0 + ty*8 + i;
        size_t off  = ((size_t)bh*LQ + q)*LK + kb;
        size_t moff = ((size_t)b *LQ + q)*LK + kb;
        int4 m0v = *(const int4*)&mask[moff];
        int4 m1v = *(const int4*)&mask[moff+4];
        float4 bi0 = *(const float4*)&bias[off];
        float4 bi1 = *(const float4*)&bias[off+4];
        float4 s0, s1;
        s0.x = m0v.x ? c[i][0]*0.125f + bi0.x : -1e9f;
        s0.y = m0v.y ? c[i][1]*0.125f + bi0.y : -1e9f;
        s0.z = m0v.z ? c[i][2]*0.125f + bi0.z : -1e9f;
        s0.w = m0v.w ? c[i][3]*0.125f + bi0.w : -1e9f;
        s1.x = m1v.x ? c[i][4]*0.125f + bi1.x : -1e9f;
        s1.y = m1v.y ? c[i][5]*0.125f + bi1.y : -1e9f;
        s1.z = m1v.z ? c[i][6]*0.125f + bi1.z : -1e9f;
        s1.w = m1v.w ? c[i][7]*0.125f + bi1.w : -1e9f;
        *(float4*)&P[off]   = s0;
        *(float4*)&P[off+4] = s1;
    }
}

// ---------------------------------------------------------------------------
// In-place row softmax over Lk=2048. One block / row, 256 threads.
// ---------------------------------------------------------------------------
__global__ void softmax_kernel(float* __restrict__ P)
{
    const size_t row = blockIdx.x;
    float* p = P + row * LK;
    const int tid = threadIdx.x;
    const int lane = tid & 31, wid = tid >> 5;

    float4 a = ((const float4*)p)[tid];
    float4 c = ((const float4*)p)[tid + 256];

    float m = fmaxf(fmaxf(fmaxf(a.x,a.y),fmaxf(a.z,a.w)),
                    fmaxf(fmaxf(c.x,c.y),fmaxf(c.z,c.w)));
    #pragma unroll
    for (int o = 16; o > 0; o >>= 1) m = fmaxf(m, __shfl_xor_sync(0xffffffffu, m, o));
    __shared__ float red[8];
    if (lane == 0) red[wid] = m;
    __syncthreads();
    float mm = red[0];
    #pragma unroll
    for (int i = 1; i < 8; i++) mm = fmaxf(mm, red[i]);
    __syncthreads();

    a.x = __expf(a.x - mm); a.y = __expf(a.y - mm);
    a.z = __expf(a.z - mm); a.w = __expf(a.w - mm);
    c.x = __expf(c.x - mm); c.y = __expf(c.y - mm);
    c.z = __expf(c.z - mm); c.w = __expf(c.w - mm);

    float s = a.x + a.y + a.z + a.w + c.x + c.y + c.z + c.w;
    #pragma unroll
    for (int o = 16; o > 0; o >>= 1) s += __shfl_xor_sync(0xffffffffu, s, o);
    if (lane == 0) red[wid] = s;
    __syncthreads();
    float tot = red[0];
    #pragma unroll
    for (int i = 1; i < 8; i++) tot += red[i];
    float inv = __frcp_rn(tot);

    a.x *= inv; a.y *= inv; a.z *= inv; a.w *= inv;
    c.x *= inv; c.y *= inv; c.z *= inv; c.w *= inv;
    ((float4*)p)[tid]       = a;
    ((float4*)p)[tid + 256] = c;
}

// ---------------------------------------------------------------------------
// Ctx[b,q, h*64+d] = sum_k P[b,h,q,k] * V[b,h,k,d]
// 128(q) x 64(d) tile, BK=16, 8x4 microtile, fma2.
// ---------------------------------------------------------------------------
__global__ __launch_bounds__(256, 2)
void av_kernel(const float* __restrict__ P, float* __restrict__ Ctx)
{
    const int bh = blockIdx.y;
    const int b  = bh / NH, h = bh - b*NH;
    const int q0 = blockIdx.x * 128;
    __shared__ __align__(16) float Ps[16][132];   // [kk][q]
    __shared__ __align__(16) float Vs[16][68];    // [kk][d]
    __shared__ __align__(16) float Vw[16][68];    // pair-swapped along d
    const float* Pg = P + ((size_t)bh*LQ + q0) * LK;
    const float* Vg = g_V + (size_t)bh * LK * DH;
    const int tid = threadIdx.x, tx = tid & 15, ty = tid >> 4;

    u64 accD[4][2], accA[4][2];
    #pragma unroll
    for (int p = 0; p < 4; p++)
        #pragma unroll
        for (int q = 0; q < 2; q++) { accD[p][q] = 0ull; accA[p][q] = 0ull; }

    for (int k0 = 0; k0 < LK; k0 += 16) {
        #pragma unroll
        for (int it = 0; it < 2; it++) {
            int g = tid + it * 256;       // 0..511
            int r = g >> 2;               // q 0..127
            int cc = (g & 3) * 4;         // k-offset 0,4,8,12
            float4 pv = *(const float4*)(Pg + (size_t)r*LK + k0 + cc);
            Ps[cc+0][r]=pv.x; Ps[cc+1][r]=pv.y; Ps[cc+2][r]=pv.z; Ps[cc+3][r]=pv.w;
        }
        {
            int kk = tid >> 4;            // 0..15
            int cc = (tid & 15) * 4;      // d 0..60
            float4 vv = *(const float4*)(Vg + (size_t)(k0+kk)*DH + cc);
            *(float4*)&Vs[kk][cc] = vv;
            *(float4*)&Vw[kk][cc] = make_float4(vv.y, vv.x, vv.w, vv.z);
        }
        __syncthreads();
        #pragma unroll
        for (int kk = 0; kk < 16; kk++) {
            ulonglong2 a01 = *(const ulonglong2*)&Ps[kk][ty*8];
            ulonglong2 a23 = *(const ulonglong2*)&Ps[kk][ty*8+4];
            ulonglong2 bv  = *(const ulonglong2*)&Vs[kk][tx*4];
            ulonglong2 wv  = *(const ulonglong2*)&Vw[kk][tx*4];
            u64 ap[4] = {a01.x, a01.y, a23.x, a23.y};
            u64 bp[2] = {bv.x, bv.y};
            u64 bw[2] = {wv.x, wv.y};
            #pragma unroll
            for (int p = 0; p < 4; p++)
                #pragma unroll
                for (int q = 0; q < 2; q++) {
                    accD[p][q] = fma2(ap[p], bp[q], accD[p][q]);
                    accA[p][q] = fma2(ap[p], bw[q], accA[p][q]);
                }
        }
        __syncthreads();
    }

    float c[8][4];
    #pragma unroll
    for (int p = 0; p < 4; p++)
        #pragma unroll
        for (int q = 0; q < 2; q++) {
            float2 d_ = u2f(accD[p][q]);
            float2 a_ = u2f(accA[p][q]);
            c[2*p  ][2*q  ] = d_.x;
            c[2*p+1][2*q+1] = d_.y;
            c[2*p  ][2*q+1] = a_.x;
            c[2*p+1][2*q  ] = a_.y;
        }

    #pragma unroll
    for (int i = 0; i < 8; i++) {
        int q = q0 + ty*8 + i;
        float* o = Ctx + ((size_t)b*LQ + q)*DM + h*DH + tx*4;
        *(float4*)o = make_float4(c[i][0], c[i][1], c[i][2], c[i][3]);
    }
}

// ---------------------------------------------------------------------------
extern "C" void kernel_launch(void* const* d_in, const int* in_sizes, int n_in,
                              void* d_out, int out_size)
{
    const float* query = (const float*)d_in[0];
    const float* key   = (const float*)d_in[1];
    const float* value = (const float*)d_in[2];
    const int*   mask  = (const int*)  d_in[3];
    const float* abias = (const float*)d_in[4];
    const float* Wq = (const float*)d_in[5];  const float* bq = (const float*)d_in[6];
    const float* Wk = (const float*)d_in[7];  const float* bk = (const float*)d_in[8];
    const float* Wv = (const float*)d_in[9];  const float* bv = (const float*)d_in[10];
    const float* Wo = (const float*)d_in[11]; const float* bo = (const float*)d_in[12];

    float* out = (float*)d_out;
    const long long OUT_ELEMS  = (long long)B_*LQ*DM;
    const long long ATTN_ELEMS = (long long)B_*NH*LQ*LK;

    float* attn;
    if ((long long)out_size >= OUT_ELEMS + ATTN_ELEMS) {
        attn = out + OUT_ELEMS;
    } else {
        void* p = nullptr;
        cudaGetSymbolAddress(&p, g_attn_fallback);
        attn = (float*)p;
    }

    float *gq, *gk, *gv, *gctx;
    { void* p; cudaGetSymbolAddress(&p, g_Q);   gq   = (float*)p; }
    { void* p; cudaGetSymbolAddress(&p, g_K);   gk   = (float*)p; }
    { void* p; cudaGetSymbolAddress(&p, g_V);   gv   = (float*)p; }
    { void* p; cudaGetSymbolAddress(&p, g_Ctx); gctx = (float*)p; }

    // 1) projections into head-split layout
    proj_gemm<<<dim3(DM/128, (B_*LQ)/128), 256>>>(query, Wq, bq, gq, LQ, 1);
    proj_gemm<<<dim3(DM/128, (B_*LK)/128), 256>>>(key,   Wk, bk, gk, LK, 1);
    proj_gemm<<<dim3(DM/128, (B_*LK)/128), 256>>>(value, Wv, bv, gv, LK, 1);

    // 2) scores = QK^T/8 + bias, masked
    scores_kernel<<<dim3(LK/128, LQ/128, B_*NH), 256>>>(mask, abias, attn);

    // 3) softmax rows (in place -> final attn output)
    softmax_kernel<<<B_*NH*LQ, 256>>>(attn);

    // 4) context = attn @ V
    av_kernel<<<dim3(LQ/128, B_*NH), 256>>>(attn, gctx);

    // 5) output projection
    proj_gemm<<<dim3(DM/128, (B_*LQ)/128), 256>>>(gctx, Wo, bo, out, LQ, 0);
}